// round 1
// baseline (speedup 1.0000x reference)
#include <cuda_runtime.h>
#include <math.h>

#define BB 4
#define CC 256
#define SS 4096            // H*W
#define NH 4
#define HD 64              // head dim
#define GROUPS 32
#define CPG 8              // channels per group
#define EPS 1e-5f
#define RSQRT2 0.70710678118654752440f

// Scratch (static device memory: allowed; no runtime allocation)
__device__ float g_norm[BB * CC * SS];        // 16.8 MB
__device__ float g_qkv[BB * 3 * CC * SS];     // 50.3 MB
__device__ float g_att[BB * CC * SS];         // 16.8 MB

// ---------------------------------------------------------------------------
// Kernel 1: GroupNorm.  128 blocks = (B=4) x (GROUPS=32), 256 threads.
// Each block normalizes 8 channels x 4096 = 32768 floats.
// ---------------------------------------------------------------------------
__global__ __launch_bounds__(256) void gn_kernel(const float* __restrict__ x,
                                                 const float* __restrict__ gamma,
                                                 const float* __restrict__ beta) {
    const int b = blockIdx.x >> 5;
    const int g = blockIdx.x & 31;
    const int n = CPG * SS;                       // 32768
    const size_t base = ((size_t)b * CC + (size_t)g * CPG) * SS;
    const float4* x4 = (const float4*)(x + base);

    float s = 0.f, ss = 0.f;
    for (int i = threadIdx.x; i < n / 4; i += 256) {
        float4 v = x4[i];
        s  += v.x + v.y + v.z + v.w;
        ss += v.x * v.x + v.y * v.y + v.z * v.z + v.w * v.w;
    }
    // warp reduce then block reduce
    #pragma unroll
    for (int w = 16; w > 0; w >>= 1) {
        s  += __shfl_xor_sync(0xffffffffu, s, w);
        ss += __shfl_xor_sync(0xffffffffu, ss, w);
    }
    __shared__ float rs[8], rss[8];
    __shared__ float s_mean, s_rstd;
    const int wid = threadIdx.x >> 5;
    if ((threadIdx.x & 31) == 0) { rs[wid] = s; rss[wid] = ss; }
    __syncthreads();
    if (threadIdx.x == 0) {
        float ts = 0.f, tss = 0.f;
        #pragma unroll
        for (int i = 0; i < 8; i++) { ts += rs[i]; tss += rss[i]; }
        float mean = ts / (float)n;
        float var  = tss / (float)n - mean * mean;
        s_mean = mean;
        s_rstd = rsqrtf(var + EPS);
    }
    __syncthreads();
    const float mean = s_mean, rstd = s_rstd;

    float4* o4 = (float4*)(g_norm + base);
    for (int i = threadIdx.x; i < n / 4; i += 256) {
        int c = g * CPG + (i >> 10);              // i*4 / 4096
        float ga = gamma[c], be = beta[c];
        float4 v = x4[i];
        v.x = (v.x - mean) * rstd * ga + be;
        v.y = (v.y - mean) * rstd * ga + be;
        v.z = (v.z - mean) * rstd * ga + be;
        v.w = (v.w - mean) * rstd * ga + be;
        o4[i] = v;
    }
}

// ---------------------------------------------------------------------------
// Kernel 2: QKV 1x1 conv = GEMM  qkv[b,o,s] = sum_c w[o,c]*norm[b,c,s] + bias[o]
// Tile 64(o) x 64(s), TK=16, 256 threads, 4x4 microtile.
// grid = (4096/64, 768/64, B)
// ---------------------------------------------------------------------------
__global__ __launch_bounds__(256) void qkv_kernel(const float* __restrict__ w,
                                                  const float* __restrict__ bias) {
    __shared__ float sA[16][64];   // [k][o]
    __shared__ float sB[16][64];   // [k][s]
    const int b  = blockIdx.z;
    const int o0 = blockIdx.y * 64;
    const int s0 = blockIdx.x * 64;
    const float* Bm = g_norm + (size_t)b * CC * SS;
    const int tid = threadIdx.x;
    const int ty = tid >> 4, tx = tid & 15;

    float acc[4][4] = {};
    const int ar = tid >> 2;            // A row 0..63
    const int ak = (tid & 3) * 4;       // A k offset
    const int br = tid >> 4;            // B row 0..15
    const int bc = (tid & 15) * 4;      // B col offset

    for (int kb = 0; kb < CC; kb += 16) {
        float4 av = *(const float4*)(w + (size_t)(o0 + ar) * CC + kb + ak);
        sA[ak + 0][ar] = av.x;
        sA[ak + 1][ar] = av.y;
        sA[ak + 2][ar] = av.z;
        sA[ak + 3][ar] = av.w;
        *(float4*)&sB[br][bc] = *(const float4*)(Bm + (size_t)(kb + br) * SS + s0 + bc);
        __syncthreads();
        #pragma unroll
        for (int kk = 0; kk < 16; kk++) {
            float4 a  = *(const float4*)&sA[kk][ty * 4];
            float4 bq = *(const float4*)&sB[kk][tx * 4];
            float aa[4] = {a.x, a.y, a.z, a.w};
            float bb[4] = {bq.x, bq.y, bq.z, bq.w};
            #pragma unroll
            for (int i = 0; i < 4; i++)
                #pragma unroll
                for (int j = 0; j < 4; j++)
                    acc[i][j] += aa[i] * bb[j];
        }
        __syncthreads();
    }
    #pragma unroll
    for (int i = 0; i < 4; i++) {
        int o = o0 + ty * 4 + i;
        float bo = bias[o];
        float4 st = {acc[i][0] + bo, acc[i][1] + bo, acc[i][2] + bo, acc[i][3] + bo};
        *(float4*)(g_qkv + ((size_t)b * 768 + o) * SS + s0 + tx * 4) = st;
    }
}

// ---------------------------------------------------------------------------
// Kernel 3: flash attention.  grid = (S/128, NH, B), 256 threads, 2 CTA/SM.
// Bq=128 queries per CTA, Bk=64 keys per tile, d=64.
// smem (floats): sQ[64][128] | sK[64][64] | sVt[64][65] | sP[128*64 / 64*129]
// ---------------------------------------------------------------------------
#define SM_Q   0
#define SM_K   8192
#define SM_V   12288
#define SM_P   16448
#define SM_TOT 24704           // floats -> 98816 bytes

__global__ __launch_bounds__(256, 2) void attn_kernel() {
    extern __shared__ float sm[];
    float* sQ = sm + SM_Q;     // [d][q] row stride 128
    float* sK = sm + SM_K;     // [d][k] row stride 64
    float* sV = sm + SM_V;     // [k][d] row stride 65 (transposed V)
    float* sP = sm + SM_P;     // [q][k] stride 64; reused as [d][q] stride 129

    const int tid = threadIdx.x;
    const int b = blockIdx.z, n = blockIdx.y;
    const int q0 = blockIdx.x * 128;
    const float* qb = g_qkv + ((size_t)b * 768 + (size_t)n * 192) * SS;
    const float* kb = qb + (size_t)64 * SS;
    const float* vb = qb + (size_t)128 * SS;

    // Load Q tile, scaled by 1/sqrt(C) = 1/16
    #pragma unroll
    for (int i = 0; i < 8; i++) {
        int li = tid + i * 256;            // 0..2047 (float4 units)
        int d = li >> 5, c = li & 31;
        float4 v = *(const float4*)(qb + (size_t)d * SS + q0 + c * 4);
        v.x *= 0.0625f; v.y *= 0.0625f; v.z *= 0.0625f; v.w *= 0.0625f;
        *(float4*)&sQ[d * 128 + c * 4] = v;
    }

    const int ty = tid >> 4, tx = tid & 15;   // ty: q-group (8 rows), tx: k/d-group (4 cols)
    float m[8], l[8], acc[8][4];
    #pragma unroll
    for (int i = 0; i < 8; i++) {
        m[i] = -1e30f; l[i] = 0.f;
        acc[i][0] = acc[i][1] = acc[i][2] = acc[i][3] = 0.f;
    }

    for (int kt = 0; kt < 64; kt++) {
        const int k0 = kt * 64;
        __syncthreads();   // prev-iter PV reads of sV/sP done before overwrite
        #pragma unroll
        for (int i = 0; i < 4; i++) {
            int li = tid + i * 256;        // 0..1023 (float4 units)
            int d = li >> 4, c = li & 15;
            *(float4*)&sK[d * 64 + c * 4] = *(const float4*)(kb + (size_t)d * SS + k0 + c * 4);
            float4 vv = *(const float4*)(vb + (size_t)d * SS + k0 + c * 4);
            sV[(c * 4 + 0) * 65 + d] = vv.x;
            sV[(c * 4 + 1) * 65 + d] = vv.y;
            sV[(c * 4 + 2) * 65 + d] = vv.z;
            sV[(c * 4 + 3) * 65 + d] = vv.w;
        }
        __syncthreads();

        // --- scores: S[128q x 64k] ---
        float sc[8][4] = {};
        #pragma unroll 16
        for (int d = 0; d < 64; d++) {
            float4 a0 = *(const float4*)&sQ[d * 128 + ty * 8];
            float4 a1 = *(const float4*)&sQ[d * 128 + ty * 8 + 4];
            float4 bk = *(const float4*)&sK[d * 64 + tx * 4];
            float aa[8] = {a0.x, a0.y, a0.z, a0.w, a1.x, a1.y, a1.z, a1.w};
            float bb[4] = {bk.x, bk.y, bk.z, bk.w};
            #pragma unroll
            for (int i = 0; i < 8; i++)
                #pragma unroll
                for (int j = 0; j < 4; j++)
                    sc[i][j] += aa[i] * bb[j];
        }

        // --- online softmax (row stats across 16 tx lanes via shfl) ---
        #pragma unroll
        for (int i = 0; i < 8; i++) {
            float tm = fmaxf(fmaxf(sc[i][0], sc[i][1]), fmaxf(sc[i][2], sc[i][3]));
            tm = fmaxf(tm, __shfl_xor_sync(0xffffffffu, tm, 1));
            tm = fmaxf(tm, __shfl_xor_sync(0xffffffffu, tm, 2));
            tm = fmaxf(tm, __shfl_xor_sync(0xffffffffu, tm, 4));
            tm = fmaxf(tm, __shfl_xor_sync(0xffffffffu, tm, 8));
            float mn = fmaxf(m[i], tm);
            float alpha = __expf(m[i] - mn);
            float p0 = __expf(sc[i][0] - mn);
            float p1 = __expf(sc[i][1] - mn);
            float p2 = __expf(sc[i][2] - mn);
            float p3 = __expf(sc[i][3] - mn);
            float ps = p0 + p1 + p2 + p3;
            ps += __shfl_xor_sync(0xffffffffu, ps, 1);
            ps += __shfl_xor_sync(0xffffffffu, ps, 2);
            ps += __shfl_xor_sync(0xffffffffu, ps, 4);
            ps += __shfl_xor_sync(0xffffffffu, ps, 8);
            l[i] = l[i] * alpha + ps;
            m[i] = mn;
            acc[i][0] *= alpha; acc[i][1] *= alpha;
            acc[i][2] *= alpha; acc[i][3] *= alpha;
            float4 pv = {p0, p1, p2, p3};
            *(float4*)&sP[(ty * 8 + i) * 64 + tx * 4] = pv;
        }
        __syncthreads();

        // --- PV: acc[8q][4d] += P[q][kk] * V[kk][d] ---
        #pragma unroll 4
        for (int kk = 0; kk < 64; kk++) {
            float v0 = sV[kk * 65 + tx * 4 + 0];
            float v1 = sV[kk * 65 + tx * 4 + 1];
            float v2 = sV[kk * 65 + tx * 4 + 2];
            float v3 = sV[kk * 65 + tx * 4 + 3];
            #pragma unroll
            for (int i = 0; i < 8; i++) {
                float p = sP[(ty * 8 + i) * 64 + kk];
                acc[i][0] += p * v0;
                acc[i][1] += p * v1;
                acc[i][2] += p * v2;
                acc[i][3] += p * v3;
            }
        }
    }
    __syncthreads();

    // Normalize and transpose through smem for coalesced channel-major store
    #pragma unroll
    for (int i = 0; i < 8; i++) {
        float inv = 1.f / l[i];
        #pragma unroll
        for (int j = 0; j < 4; j++)
            sP[(tx * 4 + j) * 129 + ty * 8 + i] = acc[i][j] * inv;
    }
    __syncthreads();
    #pragma unroll
    for (int i = 0; i < 32; i++) {
        int li = tid + i * 256;            // 0..8191
        int d = li >> 7, c = li & 127;
        g_att[((size_t)b * 256 + (size_t)n * 64 + d) * SS + q0 + c] = sP[d * 129 + c];
    }
}

// ---------------------------------------------------------------------------
// Kernel 4: out 1x1 conv + bias + residual + /sqrt(2)
// out[b,o,s] = (sum_c w[o,c]*att[b,c,s] + bias[o] + x[b,o,s]) * rsqrt2
// grid = (4096/64, 256/64, B)
// ---------------------------------------------------------------------------
__global__ __launch_bounds__(256) void out_kernel(const float* __restrict__ w,
                                                  const float* __restrict__ bias,
                                                  const float* __restrict__ x,
                                                  float* __restrict__ out) {
    __shared__ float sA[16][64];
    __shared__ float sB[16][64];
    const int b  = blockIdx.z;
    const int o0 = blockIdx.y * 64;
    const int s0 = blockIdx.x * 64;
    const float* Bm = g_att + (size_t)b * CC * SS;
    const int tid = threadIdx.x;
    const int ty = tid >> 4, tx = tid & 15;

    float acc[4][4] = {};
    const int ar = tid >> 2;
    const int ak = (tid & 3) * 4;
    const int br = tid >> 4;
    const int bc = (tid & 15) * 4;

    for (int kb = 0; kb < CC; kb += 16) {
        float4 av = *(const float4*)(w + (size_t)(o0 + ar) * CC + kb + ak);
        sA[ak + 0][ar] = av.x;
        sA[ak + 1][ar] = av.y;
        sA[ak + 2][ar] = av.z;
        sA[ak + 3][ar] = av.w;
        *(float4*)&sB[br][bc] = *(const float4*)(Bm + (size_t)(kb + br) * SS + s0 + bc);
        __syncthreads();
        #pragma unroll
        for (int kk = 0; kk < 16; kk++) {
            float4 a  = *(const float4*)&sA[kk][ty * 4];
            float4 bq = *(const float4*)&sB[kk][tx * 4];
            float aa[4] = {a.x, a.y, a.z, a.w};
            float bb[4] = {bq.x, bq.y, bq.z, bq.w};
            #pragma unroll
            for (int i = 0; i < 4; i++)
                #pragma unroll
                for (int j = 0; j < 4; j++)
                    acc[i][j] += aa[i] * bb[j];
        }
        __syncthreads();
    }
    #pragma unroll
    for (int i = 0; i < 4; i++) {
        int o = o0 + ty * 4 + i;
        float bo = bias[o];
        size_t base = ((size_t)b * CC + o) * SS + s0 + tx * 4;
        float4 xv = *(const float4*)(x + base);
        float4 st;
        st.x = (acc[i][0] + bo + xv.x) * RSQRT2;
        st.y = (acc[i][1] + bo + xv.y) * RSQRT2;
        st.z = (acc[i][2] + bo + xv.z) * RSQRT2;
        st.w = (acc[i][3] + bo + xv.w) * RSQRT2;
        *(float4*)(out + base) = st;
    }
}

// ---------------------------------------------------------------------------
// Host launch
// ---------------------------------------------------------------------------
extern "C" void kernel_launch(void* const* d_in, const int* in_sizes, int n_in,
                              void* d_out, int out_size) {
    const float* x        = (const float*)d_in[0];
    const float* gn_gamma = (const float*)d_in[1];
    const float* gn_beta  = (const float*)d_in[2];
    const float* w_qkv    = (const float*)d_in[3];
    const float* b_qkv    = (const float*)d_in[4];
    const float* w_out    = (const float*)d_in[5];
    const float* b_out    = (const float*)d_in[6];
    float* out = (float*)d_out;

    cudaFuncSetAttribute(attn_kernel, cudaFuncAttributeMaxDynamicSharedMemorySize,
                         SM_TOT * (int)sizeof(float));

    gn_kernel<<<BB * GROUPS, 256>>>(x, gn_gamma, gn_beta);
    qkv_kernel<<<dim3(SS / 64, 768 / 64, BB), 256>>>(w_qkv, b_qkv);
    attn_kernel<<<dim3(SS / 128, NH, BB), 256, SM_TOT * (int)sizeof(float)>>>();
    out_kernel<<<dim3(SS / 64, CC / 64, BB), 256>>>(w_out, b_out, x, out);
}

// round 2
// speedup vs baseline: 3.5939x; 3.5939x over previous
#include <cuda_runtime.h>
#include <math.h>

#define BB 4
#define CC 256
#define SS 4096            // H*W
#define NH 4
#define GROUPS 32
#define CPG 8
#define EPS 1e-5f
#define RSQRT2 0.70710678118654752440f

__device__ float g_norm[BB * CC * SS];
__device__ float g_qkv[BB * 3 * CC * SS];
__device__ float g_att[BB * CC * SS];

// ---------------------------------------------------------------------------
// tf32 mma helpers
// ---------------------------------------------------------------------------
__device__ __forceinline__ unsigned f2tf(float f) {
    unsigned u;
    asm("cvt.rna.tf32.f32 %0, %1;" : "=r"(u) : "f"(f));
    return u;
}
__device__ __forceinline__ void mma8(float* c, const unsigned* a, unsigned b0, unsigned b1) {
    asm volatile(
        "mma.sync.aligned.m16n8k8.row.col.f32.tf32.tf32.f32 "
        "{%0,%1,%2,%3}, {%4,%5,%6,%7}, {%8,%9}, {%0,%1,%2,%3};"
        : "+f"(c[0]), "+f"(c[1]), "+f"(c[2]), "+f"(c[3])
        : "r"(a[0]), "r"(a[1]), "r"(a[2]), "r"(a[3]), "r"(b0), "r"(b1));
}
#define XK(j) ((((j) & 1) << 2) | ((j) >> 1))

// ---------------------------------------------------------------------------
// Kernel 1: GroupNorm (unchanged from R1)
// ---------------------------------------------------------------------------
__global__ __launch_bounds__(256) void gn_kernel(const float* __restrict__ x,
                                                 const float* __restrict__ gamma,
                                                 const float* __restrict__ beta) {
    const int b = blockIdx.x >> 5;
    const int g = blockIdx.x & 31;
    const int n = CPG * SS;
    const size_t base = ((size_t)b * CC + (size_t)g * CPG) * SS;
    const float4* x4 = (const float4*)(x + base);

    float s = 0.f, ss = 0.f;
    for (int i = threadIdx.x; i < n / 4; i += 256) {
        float4 v = x4[i];
        s  += v.x + v.y + v.z + v.w;
        ss += v.x * v.x + v.y * v.y + v.z * v.z + v.w * v.w;
    }
    #pragma unroll
    for (int w = 16; w > 0; w >>= 1) {
        s  += __shfl_xor_sync(0xffffffffu, s, w);
        ss += __shfl_xor_sync(0xffffffffu, ss, w);
    }
    __shared__ float rs[8], rss[8];
    __shared__ float s_mean, s_rstd;
    const int wid = threadIdx.x >> 5;
    if ((threadIdx.x & 31) == 0) { rs[wid] = s; rss[wid] = ss; }
    __syncthreads();
    if (threadIdx.x == 0) {
        float ts = 0.f, tss = 0.f;
        #pragma unroll
        for (int i = 0; i < 8; i++) { ts += rs[i]; tss += rss[i]; }
        float mean = ts / (float)n;
        float var  = tss / (float)n - mean * mean;
        s_mean = mean;
        s_rstd = rsqrtf(var + EPS);
    }
    __syncthreads();
    const float mean = s_mean, rstd = s_rstd;

    float4* o4 = (float4*)(g_norm + base);
    for (int i = threadIdx.x; i < n / 4; i += 256) {
        int c = g * CPG + (i >> 10);
        float ga = gamma[c], be = beta[c];
        float4 v = x4[i];
        v.x = (v.x - mean) * rstd * ga + be;
        v.y = (v.y - mean) * rstd * ga + be;
        v.z = (v.z - mean) * rstd * ga + be;
        v.w = (v.w - mean) * rstd * ga + be;
        o4[i] = v;
    }
}

// ---------------------------------------------------------------------------
// Kernel 2: QKV GEMM (unchanged from R1)
// ---------------------------------------------------------------------------
__global__ __launch_bounds__(256) void qkv_kernel(const float* __restrict__ w,
                                                  const float* __restrict__ bias) {
    __shared__ float sA[16][64];
    __shared__ float sB[16][64];
    const int b  = blockIdx.z;
    const int o0 = blockIdx.y * 64;
    const int s0 = blockIdx.x * 64;
    const float* Bm = g_norm + (size_t)b * CC * SS;
    const int tid = threadIdx.x;
    const int ty = tid >> 4, tx = tid & 15;

    float acc[4][4] = {};
    const int ar = tid >> 2;
    const int ak = (tid & 3) * 4;
    const int br = tid >> 4;
    const int bc = (tid & 15) * 4;

    for (int kb = 0; kb < CC; kb += 16) {
        float4 av = *(const float4*)(w + (size_t)(o0 + ar) * CC + kb + ak);
        sA[ak + 0][ar] = av.x;
        sA[ak + 1][ar] = av.y;
        sA[ak + 2][ar] = av.z;
        sA[ak + 3][ar] = av.w;
        *(float4*)&sB[br][bc] = *(const float4*)(Bm + (size_t)(kb + br) * SS + s0 + bc);
        __syncthreads();
        #pragma unroll
        for (int kk = 0; kk < 16; kk++) {
            float4 a  = *(const float4*)&sA[kk][ty * 4];
            float4 bq = *(const float4*)&sB[kk][tx * 4];
            float aa[4] = {a.x, a.y, a.z, a.w};
            float bb[4] = {bq.x, bq.y, bq.z, bq.w};
            #pragma unroll
            for (int i = 0; i < 4; i++)
                #pragma unroll
                for (int j = 0; j < 4; j++)
                    acc[i][j] += aa[i] * bb[j];
        }
        __syncthreads();
    }
    #pragma unroll
    for (int i = 0; i < 4; i++) {
        int o = o0 + ty * 4 + i;
        float bo = bias[o];
        float4 st = {acc[i][0] + bo, acc[i][1] + bo, acc[i][2] + bo, acc[i][3] + bo};
        *(float4*)(g_qkv + ((size_t)b * 768 + o) * SS + s0 + tx * 4) = st;
    }
}

// ---------------------------------------------------------------------------
// Kernel 3: flash attention with tf32 mma.sync (m16n8k8).
// grid = (S/128, NH, B), 256 threads (8 warps x 16 q-rows), Bk = 64.
// smem floats: sQf 8192 | sKf 4096 | sVf 4096 | sP 8*1088 -> 25088 fl = 100352 B
// ---------------------------------------------------------------------------
#define ATTN_SMEM_FLOATS 25088

__global__ __launch_bounds__(256, 2) void attn_kernel() {
    extern __shared__ float sm[];
    float* sQf = sm;               // packed A-frags: ((w*8+s)*32+lane)*4+slot
    float* sKf = sm + 8192;        // packed B-pair frags (QK)
    float* sVf = sm + 12288;       // packed B-pair frags (PV)
    float* sP  = sm + 16384;       // per-warp 16x68 P tile

    const int tid  = threadIdx.x;
    const int lane = tid & 31;
    const int w    = tid >> 5;
    const int r    = lane >> 2;    // 0..7
    const int cq   = lane & 3;     // 0..3
    const int b = blockIdx.z, hn = blockIdx.y;
    const int q0 = blockIdx.x * 128;

    const float* qg = g_qkv + ((size_t)b * 768 + hn * 192) * SS;
    const float* kg = qg + (size_t)64 * SS;
    const float* vg = qg + (size_t)128 * SS;

    // ---- pack Q (scaled by 1/sqrt(C)=1/16) into A-frag layout ----
    #pragma unroll
    for (int it = 0; it < 8; it++) {
        int i = tid + it * 256;
        int d  = i >> 5;
        int qq = (i & 31) * 4;
        float4 v = *(const float4*)(qg + (size_t)d * SS + q0 + qq);
        float vv[4] = {v.x, v.y, v.z, v.w};
        int s = d >> 3, din = d & 7;
        #pragma unroll
        for (int e = 0; e < 4; e++) {
            int q = qq + e;
            int lf   = ((q & 7) << 2) | (din & 3);
            int slot = ((q >> 3) & 1) | ((din >> 2) << 1);
            sQf[(((q >> 4) * 8 + s) * 32 + lf) * 4 + slot] =
                __uint_as_float(f2tf(vv[e] * 0.0625f));
        }
    }

    // ---- precompute K/V packed-store addresses (it-invariant parts) ----
    const int T     = tid & 15;       // key quad
    const int dbase = tid >> 4;       // 0..15
    int kaddr[4], vaddr[4];
    {
        int din = dbase & 7;
        int s0q = dbase >> 3;                       // 0/1
        #pragma unroll
        for (int e = 0; e < 4; e++) {
            int key = T * 4 + e;
            int j   = key >> 3;
            int lf  = ((key & 7) << 2) | (din & 3);
            int l2  = lf ^ XK(j);
            int slot = ((s0q & 1) << 1) | (din >> 2);
            kaddr[e] = (j * 32 + l2) * 4 + slot;    // p=0 base; +it*1024
            int sv  = key >> 3;
            int pv  = sv >> 1;
            int jv  = dbase >> 3;                   // 0/1
            int bv  = (key & 7) >> 2;
            int lfv = (din << 2) | (e & 3);
            int l2v = lfv ^ pv;
            int slv = ((sv & 1) << 1) | bv;
            vaddr[e] = ((pv * 8 + jv) * 32 + l2v) * 4 + slv;  // +it*256
        }
    }

    const float* kgp = kg + (size_t)dbase * SS + T * 4;
    const float* vgp = vg + (size_t)dbase * SS + T * 4;
    float* sPw = sP + w * 1088;

    float o[8][4];
    #pragma unroll
    for (int j = 0; j < 8; j++) { o[j][0] = o[j][1] = o[j][2] = o[j][3] = 0.f; }
    float m0 = -1e30f, m1 = -1e30f, l0 = 0.f, l1 = 0.f;

    for (int kt = 0; kt < 64; kt++) {
        const int k0 = kt * 64;
        __syncthreads();
        // ---- load + pack K, V ----
        #pragma unroll
        for (int it = 0; it < 4; it++) {
            float4 kv = *(const float4*)(kgp + (size_t)(16 * it) * SS + k0);
            float4 vv = *(const float4*)(vgp + (size_t)(16 * it) * SS + k0);
            float ka[4] = {kv.x, kv.y, kv.z, kv.w};
            float va[4] = {vv.x, vv.y, vv.z, vv.w};
            #pragma unroll
            for (int e = 0; e < 4; e++) {
                sKf[kaddr[e] + it * 1024] = __uint_as_float(f2tf(ka[e]));
                sVf[vaddr[e] + it * 256]  = __uint_as_float(f2tf(va[e]));
            }
        }
        __syncthreads();

        // ---- QK^T: sc[8 n-blocks][4] ----
        float sc[8][4];
        #pragma unroll
        for (int j = 0; j < 8; j++)
            sc[j][0] = sc[j][1] = sc[j][2] = sc[j][3] = 0.f;
        #pragma unroll
        for (int p = 0; p < 4; p++) {
            uint4 a0 = *(const uint4*)&sQf[((w * 8 + 2 * p) * 32 + lane) * 4];
            uint4 a1 = *(const uint4*)&sQf[((w * 8 + 2 * p + 1) * 32 + lane) * 4];
            unsigned A0[4] = {a0.x, a0.y, a0.z, a0.w};
            unsigned A1[4] = {a1.x, a1.y, a1.z, a1.w};
            #pragma unroll
            for (int j = 0; j < 8; j++) {
                uint4 bb = *(const uint4*)&sKf[((p * 8 + j) * 32 + (lane ^ XK(j))) * 4];
                mma8(sc[j], A0, bb.x, bb.y);
                mma8(sc[j], A1, bb.z, bb.w);
            }
        }

        // ---- online softmax (rows r and r+8) ----
        float tm0 = sc[0][0], tm1 = sc[0][2];
        #pragma unroll
        for (int j = 0; j < 8; j++) {
            tm0 = fmaxf(tm0, fmaxf(sc[j][0], sc[j][1]));
            tm1 = fmaxf(tm1, fmaxf(sc[j][2], sc[j][3]));
        }
        tm0 = fmaxf(tm0, __shfl_xor_sync(0xffffffffu, tm0, 1));
        tm0 = fmaxf(tm0, __shfl_xor_sync(0xffffffffu, tm0, 2));
        tm1 = fmaxf(tm1, __shfl_xor_sync(0xffffffffu, tm1, 1));
        tm1 = fmaxf(tm1, __shfl_xor_sync(0xffffffffu, tm1, 2));
        float mn0 = fmaxf(m0, tm0), mn1 = fmaxf(m1, tm1);
        float al0 = __expf(m0 - mn0), al1 = __expf(m1 - mn1);
        float s0 = 0.f, s1 = 0.f;
        #pragma unroll
        for (int j = 0; j < 8; j++) {
            sc[j][0] = __expf(sc[j][0] - mn0);
            sc[j][1] = __expf(sc[j][1] - mn0);
            sc[j][2] = __expf(sc[j][2] - mn1);
            sc[j][3] = __expf(sc[j][3] - mn1);
            s0 += sc[j][0] + sc[j][1];
            s1 += sc[j][2] + sc[j][3];
        }
        s0 += __shfl_xor_sync(0xffffffffu, s0, 1);
        s0 += __shfl_xor_sync(0xffffffffu, s0, 2);
        s1 += __shfl_xor_sync(0xffffffffu, s1, 1);
        s1 += __shfl_xor_sync(0xffffffffu, s1, 2);
        l0 = l0 * al0 + s0;  m0 = mn0;
        l1 = l1 * al1 + s1;  m1 = mn1;
        #pragma unroll
        for (int j = 0; j < 8; j++) {
            o[j][0] *= al0; o[j][1] *= al0;
            o[j][2] *= al1; o[j][3] *= al1;
            // store P (C-frag layout, stride 68)
            *(float2*)&sPw[r * 68 + j * 8 + 2 * cq]       = make_float2(sc[j][0], sc[j][1]);
            *(float2*)&sPw[(r + 8) * 68 + j * 8 + 2 * cq] = make_float2(sc[j][2], sc[j][3]);
        }
        __syncwarp();

        // ---- PV: o[8 d-blocks][4] += P * V ----
        #pragma unroll
        for (int pp = 0; pp < 4; pp++) {
            const int kb0 = pp * 16;
            unsigned pa0[4], pa1[4];
            pa0[0] = __float_as_uint(sPw[r * 68 + kb0 + cq]);
            pa0[1] = __float_as_uint(sPw[(r + 8) * 68 + kb0 + cq]);
            pa0[2] = __float_as_uint(sPw[r * 68 + kb0 + 4 + cq]);
            pa0[3] = __float_as_uint(sPw[(r + 8) * 68 + kb0 + 4 + cq]);
            pa1[0] = __float_as_uint(sPw[r * 68 + kb0 + 8 + cq]);
            pa1[1] = __float_as_uint(sPw[(r + 8) * 68 + kb0 + 8 + cq]);
            pa1[2] = __float_as_uint(sPw[r * 68 + kb0 + 12 + cq]);
            pa1[3] = __float_as_uint(sPw[(r + 8) * 68 + kb0 + 12 + cq]);
            #pragma unroll
            for (int j = 0; j < 8; j++) {
                uint4 bb = *(const uint4*)&sVf[((pp * 8 + j) * 32 + (lane ^ pp)) * 4];
                mma8(o[j], pa0, bb.x, bb.y);
                mma8(o[j], pa1, bb.z, bb.w);
            }
        }
    }

    // ---- epilogue: normalize, transpose via smem (stride 132), store ----
    __syncthreads();
    float inv0 = 1.f / l0, inv1 = 1.f / l1;
    float* stg = sm;
    #pragma unroll
    for (int j = 0; j < 8; j++) {
        int d0 = j * 8 + 2 * cq;
        stg[(d0 + 0) * 132 + w * 16 + r]     = o[j][0] * inv0;
        stg[(d0 + 1) * 132 + w * 16 + r]     = o[j][1] * inv0;
        stg[(d0 + 0) * 132 + w * 16 + r + 8] = o[j][2] * inv1;
        stg[(d0 + 1) * 132 + w * 16 + r + 8] = o[j][3] * inv1;
    }
    __syncthreads();
    #pragma unroll
    for (int it = 0; it < 8; it++) {
        int i = tid + it * 256;
        int d = i >> 5, c = (i & 31) * 4;
        float4 v = *(const float4*)&stg[d * 132 + c];
        *(float4*)(g_att + ((size_t)b * 256 + hn * 64 + d) * SS + q0 + c) = v;
    }
}

// ---------------------------------------------------------------------------
// Kernel 4: out GEMM + bias + residual + /sqrt(2) (unchanged from R1)
// ---------------------------------------------------------------------------
__global__ __launch_bounds__(256) void out_kernel(const float* __restrict__ w,
                                                  const float* __restrict__ bias,
                                                  const float* __restrict__ x,
                                                  float* __restrict__ out) {
    __shared__ float sA[16][64];
    __shared__ float sB[16][64];
    const int b  = blockIdx.z;
    const int o0 = blockIdx.y * 64;
    const int s0 = blockIdx.x * 64;
    const float* Bm = g_att + (size_t)b * CC * SS;
    const int tid = threadIdx.x;
    const int ty = tid >> 4, tx = tid & 15;

    float acc[4][4] = {};
    const int ar = tid >> 2;
    const int ak = (tid & 3) * 4;
    const int br = tid >> 4;
    const int bc = (tid & 15) * 4;

    for (int kb = 0; kb < CC; kb += 16) {
        float4 av = *(const float4*)(w + (size_t)(o0 + ar) * CC + kb + ak);
        sA[ak + 0][ar] = av.x;
        sA[ak + 1][ar] = av.y;
        sA[ak + 2][ar] = av.z;
        sA[ak + 3][ar] = av.w;
        *(float4*)&sB[br][bc] = *(const float4*)(Bm + (size_t)(kb + br) * SS + s0 + bc);
        __syncthreads();
        #pragma unroll
        for (int kk = 0; kk < 16; kk++) {
            float4 a  = *(const float4*)&sA[kk][ty * 4];
            float4 bq = *(const float4*)&sB[kk][tx * 4];
            float aa[4] = {a.x, a.y, a.z, a.w};
            float bb[4] = {bq.x, bq.y, bq.z, bq.w};
            #pragma unroll
            for (int i = 0; i < 4; i++)
                #pragma unroll
                for (int j = 0; j < 4; j++)
                    acc[i][j] += aa[i] * bb[j];
        }
        __syncthreads();
    }
    #pragma unroll
    for (int i = 0; i < 4; i++) {
        int o = o0 + ty * 4 + i;
        float bo = bias[o];
        size_t base = ((size_t)b * CC + o) * SS + s0 + tx * 4;
        float4 xv = *(const float4*)(x + base);
        float4 st;
        st.x = (acc[i][0] + bo + xv.x) * RSQRT2;
        st.y = (acc[i][1] + bo + xv.y) * RSQRT2;
        st.z = (acc[i][2] + bo + xv.z) * RSQRT2;
        st.w = (acc[i][3] + bo + xv.w) * RSQRT2;
        *(float4*)(out + base) = st;
    }
}

// ---------------------------------------------------------------------------
// Host launch
// ---------------------------------------------------------------------------
extern "C" void kernel_launch(void* const* d_in, const int* in_sizes, int n_in,
                              void* d_out, int out_size) {
    const float* x        = (const float*)d_in[0];
    const float* gn_gamma = (const float*)d_in[1];
    const float* gn_beta  = (const float*)d_in[2];
    const float* w_qkv    = (const float*)d_in[3];
    const float* b_qkv    = (const float*)d_in[4];
    const float* w_out    = (const float*)d_in[5];
    const float* b_out    = (const float*)d_in[6];
    float* out = (float*)d_out;

    cudaFuncSetAttribute(attn_kernel, cudaFuncAttributeMaxDynamicSharedMemorySize,
                         ATTN_SMEM_FLOATS * (int)sizeof(float));

    gn_kernel<<<BB * GROUPS, 256>>>(x, gn_gamma, gn_beta);
    qkv_kernel<<<dim3(SS / 64, 768 / 64, BB), 256>>>(w_qkv, b_qkv);
    attn_kernel<<<dim3(SS / 128, NH, BB), 256, ATTN_SMEM_FLOATS * (int)sizeof(float)>>>();
    out_kernel<<<dim3(SS / 64, CC / 64, BB), 256>>>(w_out, b_out, x, out);
}